// round 11
// baseline (speedup 1.0000x reference)
#include <cuda_runtime.h>

// Inverse 2D Haar wavelet (fused conv_transpose chain). Round-7 champion body,
// block=512 wave-shape experiment.
// x:   [8, 256, 128, 128] fp32, subbands LL | HL | LH | HH each 64 channels
// out: [8,  64, 256, 256] fp32
//
// out[2h,2w]     = 0.5*(LL+LH+HL+HH)
// out[2h,2w+1]   = 0.5*(LL-LH+HL-HH)
// out[2h+1,2w]   = 0.5*(LL+LH-HL-HH)
// out[2h+1,2w+1] = 0.5*(LL-LH-HL+HH)
//
// Each thread: one float4 of input per subband (4 x LDG.128, front-batched),
// emits TWO 256-bit stores (st.global.cs.v8.b32), one per output row.
// Consecutive threads write consecutive 32B -> perfect full-line stores.
// Stores evict_first (write-once stream).
//
// Converged at the mixed read/write HBM ceiling (~95% of 8TB/s spec counting
// trailing writebacks). Rejected: L2 persistence (3 variants), 256-bit loads,
// 2-rows/thread MLP=8. This round: block 256 -> 512 (wave shape only).

#define B_  8
#define C_  64
#define H_  128
#define W_  128
#define W4_ (W_ / 4)               // 32 float4 per row
#define IN_PLANE   (H_ * W_)       // 16384
#define IN_BSTRIDE (4 * C_ * IN_PLANE)
#define OUT_W      (2 * W_)        // 256
#define OUT_PLANE  (4 * IN_PLANE)  // 65536
#define OUT_BSTRIDE (C_ * OUT_PLANE)

__device__ __forceinline__ void st256_cs(float* p,
                                         float f0, float f1, float f2, float f3,
                                         float f4, float f5, float f6, float f7) {
    asm volatile(
        "st.global.cs.v8.b32 [%0], {%1, %2, %3, %4, %5, %6, %7, %8};"
        :: "l"(p),
           "r"(__float_as_uint(f0)), "r"(__float_as_uint(f1)),
           "r"(__float_as_uint(f2)), "r"(__float_as_uint(f3)),
           "r"(__float_as_uint(f4)), "r"(__float_as_uint(f5)),
           "r"(__float_as_uint(f6)), "r"(__float_as_uint(f7))
        : "memory");
}

__global__ __launch_bounds__(512) void iwt_kernel(const float* __restrict__ x,
                                                  float* __restrict__ out) {
    int idx = blockIdx.x * blockDim.x + threadIdx.x;
    // idx -> (b, c, h, w4)
    int w4 = idx & (W4_ - 1);
    int t  = idx >> 5;             // / 32
    int h  = t & (H_ - 1);
    t >>= 7;                       // / 128
    int c  = t & (C_ - 1);
    int b  = t >> 6;               // / 64

    const float* base = x + (long long)b * IN_BSTRIDE + (long long)c * IN_PLANE
                          + h * W_ + (w4 << 2);

    // Front-batched independent 128-bit loads, one per subband
    float4 ll = __ldg((const float4*)(base));
    float4 hl = __ldg((const float4*)(base + 64  * IN_PLANE));
    float4 lh = __ldg((const float4*)(base + 128 * IN_PLANE));
    float4 hh = __ldg((const float4*)(base + 192 * IN_PLANE));

    float* obase = out + (long long)b * OUT_BSTRIDE + (long long)c * OUT_PLANE
                       + (2 * h) * OUT_W + (w4 << 3);

    float r0[8], r1[8];

    {   // element 0 -> out cols 0,1
        float a = ll.x, bq = lh.x, cq = hl.x, d = hh.x;
        float apb = a + bq, amb = a - bq, cpd = cq + d, cmd = cq - d;
        r0[0] = 0.5f * (apb + cpd);  r0[1] = 0.5f * (amb + cmd);
        r1[0] = 0.5f * (apb - cpd);  r1[1] = 0.5f * (amb - cmd);
    }
    {   // element 1 -> out cols 2,3
        float a = ll.y, bq = lh.y, cq = hl.y, d = hh.y;
        float apb = a + bq, amb = a - bq, cpd = cq + d, cmd = cq - d;
        r0[2] = 0.5f * (apb + cpd);  r0[3] = 0.5f * (amb + cmd);
        r1[2] = 0.5f * (apb - cpd);  r1[3] = 0.5f * (amb - cmd);
    }
    {   // element 2 -> out cols 4,5
        float a = ll.z, bq = lh.z, cq = hl.z, d = hh.z;
        float apb = a + bq, amb = a - bq, cpd = cq + d, cmd = cq - d;
        r0[4] = 0.5f * (apb + cpd);  r0[5] = 0.5f * (amb + cmd);
        r1[4] = 0.5f * (apb - cpd);  r1[5] = 0.5f * (amb - cmd);
    }
    {   // element 3 -> out cols 6,7
        float a = ll.w, bq = lh.w, cq = hl.w, d = hh.w;
        float apb = a + bq, amb = a - bq, cpd = cq + d, cmd = cq - d;
        r0[6] = 0.5f * (apb + cpd);  r0[7] = 0.5f * (amb + cmd);
        r1[6] = 0.5f * (apb - cpd);  r1[7] = 0.5f * (amb - cmd);
    }

    st256_cs(obase,
             r0[0], r0[1], r0[2], r0[3], r0[4], r0[5], r0[6], r0[7]);
    st256_cs(obase + OUT_W,
             r1[0], r1[1], r1[2], r1[3], r1[4], r1[5], r1[6], r1[7]);
}

extern "C" void kernel_launch(void* const* d_in, const int* in_sizes, int n_in,
                              void* d_out, int out_size) {
    const float* x = (const float*)d_in[0];
    float* out = (float*)d_out;
    const int total = B_ * C_ * H_ * W4_;   // 2,097,152 threads
    iwt_kernel<<<total / 512, 512>>>(x, out);
}

// round 12
// speedup vs baseline: 1.0265x; 1.0265x over previous
#include <cuda_runtime.h>

// Inverse 2D Haar wavelet (fused conv_transpose chain). Round-7 champion body,
// block=256; single-variable test: default store policy (no .cs).
// x:   [8, 256, 128, 128] fp32, subbands LL | HL | LH | HH each 64 channels
// out: [8,  64, 256, 256] fp32
//
// out[2h,2w]     = 0.5*(LL+LH+HL+HH)
// out[2h,2w+1]   = 0.5*(LL-LH+HL-HH)
// out[2h+1,2w]   = 0.5*(LL+LH-HL-HH)
// out[2h+1,2w+1] = 0.5*(LL-LH-HL+HH)
//
// Each thread: one float4 of input per subband (4 x LDG.128, front-batched),
// emits TWO 256-bit stores (st.global.v8.b32), one per output row.
// Consecutive threads write consecutive 32B -> perfect full-line stores.
// Default store priority: dirty output lines linger in L2 and write back in
// scheduled bursts instead of evict_first streaming; input has no L2 reuse
// (proven R4-R6) so the pollution costs nothing.

#define B_  8
#define C_  64
#define H_  128
#define W_  128
#define W4_ (W_ / 4)               // 32 float4 per row
#define IN_PLANE   (H_ * W_)       // 16384
#define IN_BSTRIDE (4 * C_ * IN_PLANE)
#define OUT_W      (2 * W_)        // 256
#define OUT_PLANE  (4 * IN_PLANE)  // 65536
#define OUT_BSTRIDE (C_ * OUT_PLANE)

__device__ __forceinline__ void st256(float* p,
                                      float f0, float f1, float f2, float f3,
                                      float f4, float f5, float f6, float f7) {
    asm volatile(
        "st.global.v8.b32 [%0], {%1, %2, %3, %4, %5, %6, %7, %8};"
        :: "l"(p),
           "r"(__float_as_uint(f0)), "r"(__float_as_uint(f1)),
           "r"(__float_as_uint(f2)), "r"(__float_as_uint(f3)),
           "r"(__float_as_uint(f4)), "r"(__float_as_uint(f5)),
           "r"(__float_as_uint(f6)), "r"(__float_as_uint(f7))
        : "memory");
}

__global__ __launch_bounds__(256) void iwt_kernel(const float* __restrict__ x,
                                                  float* __restrict__ out) {
    int idx = blockIdx.x * blockDim.x + threadIdx.x;
    // idx -> (b, c, h, w4)
    int w4 = idx & (W4_ - 1);
    int t  = idx >> 5;             // / 32
    int h  = t & (H_ - 1);
    t >>= 7;                       // / 128
    int c  = t & (C_ - 1);
    int b  = t >> 6;               // / 64

    const float* base = x + (long long)b * IN_BSTRIDE + (long long)c * IN_PLANE
                          + h * W_ + (w4 << 2);

    // Front-batched independent 128-bit loads, one per subband
    float4 ll = __ldg((const float4*)(base));
    float4 hl = __ldg((const float4*)(base + 64  * IN_PLANE));
    float4 lh = __ldg((const float4*)(base + 128 * IN_PLANE));
    float4 hh = __ldg((const float4*)(base + 192 * IN_PLANE));

    float* obase = out + (long long)b * OUT_BSTRIDE + (long long)c * OUT_PLANE
                       + (2 * h) * OUT_W + (w4 << 3);

    float r0[8], r1[8];

    {   // element 0 -> out cols 0,1
        float a = ll.x, bq = lh.x, cq = hl.x, d = hh.x;
        float apb = a + bq, amb = a - bq, cpd = cq + d, cmd = cq - d;
        r0[0] = 0.5f * (apb + cpd);  r0[1] = 0.5f * (amb + cmd);
        r1[0] = 0.5f * (apb - cpd);  r1[1] = 0.5f * (amb - cmd);
    }
    {   // element 1 -> out cols 2,3
        float a = ll.y, bq = lh.y, cq = hl.y, d = hh.y;
        float apb = a + bq, amb = a - bq, cpd = cq + d, cmd = cq - d;
        r0[2] = 0.5f * (apb + cpd);  r0[3] = 0.5f * (amb + cmd);
        r1[2] = 0.5f * (apb - cpd);  r1[3] = 0.5f * (amb - cmd);
    }
    {   // element 2 -> out cols 4,5
        float a = ll.z, bq = lh.z, cq = hl.z, d = hh.z;
        float apb = a + bq, amb = a - bq, cpd = cq + d, cmd = cq - d;
        r0[4] = 0.5f * (apb + cpd);  r0[5] = 0.5f * (amb + cmd);
        r1[4] = 0.5f * (apb - cpd);  r1[5] = 0.5f * (amb - cmd);
    }
    {   // element 3 -> out cols 6,7
        float a = ll.w, bq = lh.w, cq = hl.w, d = hh.w;
        float apb = a + bq, amb = a - bq, cpd = cq + d, cmd = cq - d;
        r0[6] = 0.5f * (apb + cpd);  r0[7] = 0.5f * (amb + cmd);
        r1[6] = 0.5f * (apb - cpd);  r1[7] = 0.5f * (amb - cmd);
    }

    st256(obase,
          r0[0], r0[1], r0[2], r0[3], r0[4], r0[5], r0[6], r0[7]);
    st256(obase + OUT_W,
          r1[0], r1[1], r1[2], r1[3], r1[4], r1[5], r1[6], r1[7]);
}

extern "C" void kernel_launch(void* const* d_in, const int* in_sizes, int n_in,
                              void* d_out, int out_size) {
    const float* x = (const float*)d_in[0];
    float* out = (float*)d_out;
    const int total = B_ * C_ * H_ * W4_;   // 2,097,152 threads
    iwt_kernel<<<total / 256, 256>>>(x, out);
}

// round 13
// speedup vs baseline: 1.0272x; 1.0007x over previous
#include <cuda_runtime.h>

// Inverse 2D Haar wavelet (fused conv_transpose chain). FINAL — converged.
// x:   [8, 256, 128, 128] fp32, subbands LL | HL | LH | HH each 64 channels
// out: [8,  64, 256, 256] fp32
//
// out[2h,2w]     = 0.5*(LL+LH+HL+HH)
// out[2h,2w+1]   = 0.5*(LL-LH+HL-HH)
// out[2h+1,2w]   = 0.5*(LL+LH-HL-HH)
// out[2h+1,2w+1] = 0.5*(LL-LH-HL+HH)
//
// The two chained depthwise conv_transposes collapse algebraically into a
// single elementwise 4->4 butterfly (s^2 = 0.5), making this a pure streaming
// remap: 134MB read + 134MB write.
//
// Winning configuration (bench 43.49-43.52us across 6 variants; kernel
// ~35.4us = ~95% of the 8TB/s HBM spec counting trailing writebacks):
//  - one float4 of input per subband per thread (4x front-batched LDG.128)
//  - TWO 256-bit stores (st.global.cs.v8.b32), one per output row; consecutive
//    threads tile full 128B lines exactly
//  - block=256, 30 regs, occ ~78%
// Explored and rejected (all neutral/negative at the mixed R/W HBM ceiling):
// L2 persistence policies x3 (input 134MB > 126MB L2 -> circular thrash),
// 256-bit loads, 2-rows/thread MLP=8, block=512, default store policy.

#define B_  8
#define C_  64
#define H_  128
#define W_  128
#define W4_ (W_ / 4)               // 32 float4 per row
#define IN_PLANE   (H_ * W_)       // 16384
#define IN_BSTRIDE (4 * C_ * IN_PLANE)
#define OUT_W      (2 * W_)        // 256
#define OUT_PLANE  (4 * IN_PLANE)  // 65536
#define OUT_BSTRIDE (C_ * OUT_PLANE)

__device__ __forceinline__ void st256_cs(float* p,
                                         float f0, float f1, float f2, float f3,
                                         float f4, float f5, float f6, float f7) {
    asm volatile(
        "st.global.cs.v8.b32 [%0], {%1, %2, %3, %4, %5, %6, %7, %8};"
        :: "l"(p),
           "r"(__float_as_uint(f0)), "r"(__float_as_uint(f1)),
           "r"(__float_as_uint(f2)), "r"(__float_as_uint(f3)),
           "r"(__float_as_uint(f4)), "r"(__float_as_uint(f5)),
           "r"(__float_as_uint(f6)), "r"(__float_as_uint(f7))
        : "memory");
}

__global__ __launch_bounds__(256) void iwt_kernel(const float* __restrict__ x,
                                                  float* __restrict__ out) {
    int idx = blockIdx.x * blockDim.x + threadIdx.x;
    // idx -> (b, c, h, w4)
    int w4 = idx & (W4_ - 1);
    int t  = idx >> 5;             // / 32
    int h  = t & (H_ - 1);
    t >>= 7;                       // / 128
    int c  = t & (C_ - 1);
    int b  = t >> 6;               // / 64

    const float* base = x + (long long)b * IN_BSTRIDE + (long long)c * IN_PLANE
                          + h * W_ + (w4 << 2);

    // Front-batched independent 128-bit loads, one per subband
    float4 ll = __ldg((const float4*)(base));
    float4 hl = __ldg((const float4*)(base + 64  * IN_PLANE));
    float4 lh = __ldg((const float4*)(base + 128 * IN_PLANE));
    float4 hh = __ldg((const float4*)(base + 192 * IN_PLANE));

    float* obase = out + (long long)b * OUT_BSTRIDE + (long long)c * OUT_PLANE
                       + (2 * h) * OUT_W + (w4 << 3);

    float r0[8], r1[8];

    {   // element 0 -> out cols 0,1
        float a = ll.x, bq = lh.x, cq = hl.x, d = hh.x;
        float apb = a + bq, amb = a - bq, cpd = cq + d, cmd = cq - d;
        r0[0] = 0.5f * (apb + cpd);  r0[1] = 0.5f * (amb + cmd);
        r1[0] = 0.5f * (apb - cpd);  r1[1] = 0.5f * (amb - cmd);
    }
    {   // element 1 -> out cols 2,3
        float a = ll.y, bq = lh.y, cq = hl.y, d = hh.y;
        float apb = a + bq, amb = a - bq, cpd = cq + d, cmd = cq - d;
        r0[2] = 0.5f * (apb + cpd);  r0[3] = 0.5f * (amb + cmd);
        r1[2] = 0.5f * (apb - cpd);  r1[3] = 0.5f * (amb - cmd);
    }
    {   // element 2 -> out cols 4,5
        float a = ll.z, bq = lh.z, cq = hl.z, d = hh.z;
        float apb = a + bq, amb = a - bq, cpd = cq + d, cmd = cq - d;
        r0[4] = 0.5f * (apb + cpd);  r0[5] = 0.5f * (amb + cmd);
        r1[4] = 0.5f * (apb - cpd);  r1[5] = 0.5f * (amb - cmd);
    }
    {   // element 3 -> out cols 6,7
        float a = ll.w, bq = lh.w, cq = hl.w, d = hh.w;
        float apb = a + bq, amb = a - bq, cpd = cq + d, cmd = cq - d;
        r0[6] = 0.5f * (apb + cpd);  r0[7] = 0.5f * (amb + cmd);
        r1[6] = 0.5f * (apb - cpd);  r1[7] = 0.5f * (amb - cmd);
    }

    st256_cs(obase,
             r0[0], r0[1], r0[2], r0[3], r0[4], r0[5], r0[6], r0[7]);
    st256_cs(obase + OUT_W,
             r1[0], r1[1], r1[2], r1[3], r1[4], r1[5], r1[6], r1[7]);
}

extern "C" void kernel_launch(void* const* d_in, const int* in_sizes, int n_in,
                              void* d_out, int out_size) {
    const float* x = (const float*)d_in[0];
    float* out = (float*)d_out;
    const int total = B_ * C_ * H_ * W4_;   // 2,097,152 threads
    iwt_kernel<<<total / 256, 256>>>(x, out);
}